// round 12
// baseline (speedup 1.0000x reference)
#include <cuda_runtime.h>
#include <cuda_fp16.h>
#include <cstdint>

// ---------------------------------------------------------------------------
// Problem dims
// ---------------------------------------------------------------------------
#define BB   256
#define TT   128
#define CC   512
#define HID  1024
#define HOR  96
#define MM   (BB * TT)          // 32768
#define KROW 1024               // stored row length: [hi | lo] halves
#define KCH  24                 // logical K chunks of 64 halves (K_ext = 1536)
#define TIL_M 128               // = one batch (TT rows)
#define TIL_N 256
#define NSTG 2                  // 2 slots -> 96KB/CTA -> 2 CTAs/SM
#define A_STG_BYTES 16384       // 128 rows x 128B
#define B_STG_BYTES 32768       // 256 rows x 128B
#define STAGE_BYTES (A_STG_BYTES + B_STG_BYTES)        // 48KB
#define SMEM_TOTAL  (NSTG * STAGE_BYTES)               // 98304

// ---------------------------------------------------------------------------
// Scratch (__device__ globals: allocation-free rule)
// ---------------------------------------------------------------------------
__device__ __half g_Aext[(size_t)MM * KROW];    // 64 MB  [ah | al]
__device__ __half g_Bext[(size_t)HID * KROW];   //  2 MB  [bh | bl]
__device__ float  g_mem[(size_t)BB * HID];      //  1 MB

// Logical chunk -> stored column offset (halves).
// A sequence: ah(0..7), ah(0..7), al(0..7)   B sequence: bh, bl, bh
__device__ __forceinline__ int ofsA(int kc) {
    return (kc < 16) ? (kc & 7) * 64 : 512 + (kc & 7) * 64;
}
__device__ __forceinline__ int ofsB(int kc) {
    return (kc < 8) ? kc * 64 : ((kc < 16) ? 512 + (kc & 7) * 64 : (kc & 7) * 64);
}

// ---------------------------------------------------------------------------
// Baseline-PTX helpers (sm_80-level: valid on .target sm_103)
// ---------------------------------------------------------------------------
__device__ __forceinline__ uint32_t smem_u32_of(const void* p) {
    uint32_t a;
    asm("{ .reg .u64 t; cvta.to.shared.u64 t, %1; cvt.u32.u64 %0, t; }"
        : "=r"(a) : "l"(p));
    return a;
}
__device__ __forceinline__ void cp16(uint32_t dst, const void* src) {
    asm volatile("cp.async.cg.shared.global [%0], [%1], 16;"
                 :: "r"(dst), "l"(src) : "memory");
}
__device__ __forceinline__ void cp_commit() {
    asm volatile("cp.async.commit_group;" ::: "memory");
}
__device__ __forceinline__ void ldsm4(uint32_t* r, uint32_t addr) {
    asm volatile("ldmatrix.sync.aligned.m8n8.x4.shared.b16 {%0,%1,%2,%3}, [%4];"
                 : "=r"(r[0]), "=r"(r[1]), "=r"(r[2]), "=r"(r[3]) : "r"(addr));
}
__device__ __forceinline__ void mma16816(float* c, const uint32_t* a,
                                         uint32_t b0, uint32_t b1) {
    asm volatile(
        "mma.sync.aligned.m16n8k16.row.col.f32.f16.f16.f32 "
        "{%0,%1,%2,%3}, {%4,%5,%6,%7}, {%8,%9}, {%0,%1,%2,%3};"
        : "+f"(c[0]), "+f"(c[1]), "+f"(c[2]), "+f"(c[3])
        : "r"(a[0]), "r"(a[1]), "r"(a[2]), "r"(a[3]), "r"(b0), "r"(b1));
}

// ---------------------------------------------------------------------------
// fp16 split pack helpers
// ---------------------------------------------------------------------------
__device__ __forceinline__ uint2 pack4(__half a, __half b, __half c, __half d) {
    __half2 p0 = __halves2half2(a, b);
    __half2 p1 = __halves2half2(c, d);
    uint2 u;
    u.x = *reinterpret_cast<uint32_t*>(&p0);
    u.y = *reinterpret_cast<uint32_t*>(&p1);
    return u;
}
__device__ __forceinline__ void split1(float f, __half& hi, __half& lo) {
    hi = __float2half_rn(f);
    lo = __float2half_rn(f - __half2float(hi));
}

// ---------------------------------------------------------------------------
// Kernel 0a: x [MM,CC] f32 -> g_Aext [MM, 1024] = [ah | al]
// ---------------------------------------------------------------------------
__global__ __launch_bounds__(256) void convert_x_kernel(const float* __restrict__ x)
{
    const int i = blockIdx.x * 256 + threadIdx.x;   // one float4 group
    const float4 v = reinterpret_cast<const float4*>(x)[i];
    const int m  = i >> 7;          // CC/4 = 128 groups per row
    const int k4 = i & 127;
    __half h0, h1, h2, h3, l0, l1, l2, l3;
    split1(v.x, h0, l0); split1(v.y, h1, l1);
    split1(v.z, h2, l2); split1(v.w, h3, l3);
    uint2* dst = reinterpret_cast<uint2*>(g_Aext + (size_t)m * KROW);
    dst[k4]       = pack4(h0, h1, h2, h3);   // cols   0- 511: ah
    dst[128 + k4] = pack4(l0, l1, l2, l3);   // cols 512-1023: al
}

// Kernel 0b: W1 [HID,CC] f32 -> g_Bext [HID, 1024] = [bh | bl]
__global__ __launch_bounds__(256) void convert_w_kernel(const float* __restrict__ w)
{
    const int i = blockIdx.x * 256 + threadIdx.x;   // < HID*CC/4 = 131072
    const float4 v = reinterpret_cast<const float4*>(w)[i];
    const int n  = i >> 7;
    const int k4 = i & 127;
    __half h0, h1, h2, h3, l0, l1, l2, l3;
    split1(v.x, h0, l0); split1(v.y, h1, l1);
    split1(v.z, h2, l2); split1(v.w, h3, l3);
    uint2* dst = reinterpret_cast<uint2*>(g_Bext + (size_t)n * KROW);
    dst[k4]       = pack4(h0, h1, h2, h3);   // bh
    dst[128 + k4] = pack4(l0, l1, l2, l3);   // bl
}

// ---------------------------------------------------------------------------
// Kernel 1: HMMA GEMM 128x256 per CTA (warp tile 64x64), 2 CTAs/SM
// (16 warps/SM, crossbar ~86 B/cyc), 2-slot pipeline, depth-1 prefetch,
// one __syncthreads per chunk, fused leaky scan (two N-halves).
// Per-element accumulation order identical to all prior passing rounds.
// ---------------------------------------------------------------------------
__device__ __forceinline__ void load_stage(uint32_t smem_base, int s, int kc,
                                           int bm, int bn, int tid)
{
    const uint32_t sa = smem_base + s * STAGE_BYTES;
    const uint32_t sb = sa + A_STG_BYTES;
    const __half* ga = g_Aext + (size_t)bm * KROW + ofsA(kc);
    const __half* gb = g_Bext + (size_t)bn * KROW + ofsB(kc);
    // A: 128 rows x 8 chunks of 16B -> 1024 chunks, 4 per thread
#pragma unroll
    for (int j = 0; j < 4; j++) {
        const int idx = tid + j * 256;
        const int r = idx >> 3;
        const int c = idx & 7;
        uint32_t off = r * 128 + c * 16;
        off ^= (off >> 3) & 0x70;
        cp16(sa + off, ga + (size_t)r * KROW + c * 8);
    }
    // B: 256 rows x 8 chunks -> 2048 chunks, 8 per thread
#pragma unroll
    for (int j = 0; j < 8; j++) {
        const int idx = tid + j * 256;
        const int r = idx >> 3;
        const int c = idx & 7;
        uint32_t off = r * 128 + c * 16;
        off ^= (off >> 3) & 0x70;
        cp16(sb + off, gb + (size_t)r * KROW + c * 8);
    }
}

__global__ __launch_bounds__(256, 2) void gemm_scan_kernel(
    const float* __restrict__ b1, const float* __restrict__ beta_p)
{
    extern __shared__ char smem[];
    const uint32_t smem_base = smem_u32_of(smem);
    const int tid  = threadIdx.x;
    const int lane = tid & 31;
    const int wid  = tid >> 5;
    const int wm   = wid >> 2;      // 0..1 : warp row (64 M each)
    const int wn   = wid & 3;       // 0..3 : warp col (64 N each)
    const int bm = blockIdx.y * TIL_M;
    const int bn = blockIdx.x * TIL_N;

    float c[4][8][4];               // warp tile 64x64: 4 m16 x 8 n8 frags
#pragma unroll
    for (int i = 0; i < 4; i++)
#pragma unroll
        for (int j = 0; j < 8; j++)
#pragma unroll
            for (int q = 0; q < 4; q++) c[i][j][q] = 0.0f;

    // prologue: fill slot 0 (depth-1 prefetch)
    load_stage(smem_base, 0, 0, bm, bn, tid);
    cp_commit();

    for (int kc = 0; kc < KCH; kc++) {
        asm volatile("cp.async.wait_group 0;" ::: "memory");  // chunk kc landed
        __syncthreads();   // + slot (kc+1)&1's previous contents fully consumed

        // issue next prefetch BEFORE compute so LDGSTS overlaps the MMAs
        if (kc + 1 < KCH) {
            load_stage(smem_base, (kc + 1) & 1, kc + 1, bm, bn, tid);
            cp_commit();
        }

        const uint32_t sa = smem_base + (kc & 1) * STAGE_BYTES;
        const uint32_t sb = sa + A_STG_BYTES;

#pragma unroll
        for (int ks = 0; ks < 4; ks++) {      // 4 x k16 per 64-half chunk
            uint32_t af[4][4], bf[4][4];
            const uint32_t colb = ks * 32 + ((lane >> 4) << 4);  // byte col
#pragma unroll
            for (int i = 0; i < 4; i++) {
                uint32_t row = wm * 64 + i * 16 + (lane & 15);
                uint32_t off = row * 128 + colb;
                off ^= (off >> 3) & 0x70;
                ldsm4(af[i], sa + off);
            }
#pragma unroll
            for (int j = 0; j < 4; j++) {     // each covers 2 n8 frags
                uint32_t row = wn * 64 + j * 16 + (lane & 15);
                uint32_t off = row * 128 + colb;
                off ^= (off >> 3) & 0x70;
                ldsm4(bf[j], sb + off);
            }
#pragma unroll
            for (int i = 0; i < 4; i++)
#pragma unroll
                for (int j = 0; j < 4; j++) {
                    mma16816(c[i][2 * j],     af[i], bf[j][0], bf[j][2]);
                    mma16816(c[i][2 * j + 1], af[i], bf[j][1], bf[j][3]);
                }
        }
    }
    __syncthreads();   // all compute done before smem is reused as fp32 buffer

    // --------- fused epilogue + scan, two N-halves of 128 cols ---------
    float* sf = reinterpret_cast<float*>(smem);   // [128][129] fp32 = 66KB
    const float beta_c = fminf(fmaxf(beta_p[0], 0.0f), 1.0f);

#pragma unroll
    for (int half = 0; half < 2; half++) {
        // warps owning this half (wn in {2*half, 2*half+1}) write their frags
        if ((wn >> 1) == half) {
#pragma unroll
            for (int i = 0; i < 4; i++) {
                const int r0 = wm * 64 + i * 16 + (lane >> 2);
#pragma unroll
                for (int j = 0; j < 8; j++) {
                    const int col = (wn & 1) * 64 + j * 8 + ((lane & 3) << 1);
                    sf[r0 * 129 + col]           = c[i][j][0];
                    sf[r0 * 129 + col + 1]       = c[i][j][1];
                    sf[(r0 + 8) * 129 + col]     = c[i][j][2];
                    sf[(r0 + 8) * 129 + col + 1] = c[i][j][3];
                }
            }
        }
        __syncthreads();

        if (tid < 128) {
            const int h = half * 128 + tid;          // col within CTA tile
            const float bias_h = b1[bn + h];
            float mem = 0.0f;
#pragma unroll 8
            for (int t = 0; t < TT; t++) {
                const float inp   = sf[t * 129 + tid] + bias_h;
                const float reset = (mem > 1.0f) ? 1.0f : 0.0f;   // THR = 1.0
                mem = fmaf(beta_c, mem, inp - reset);
            }
            g_mem[(size_t)blockIdx.y * HID + bn + h] = mem;
        }
        __syncthreads();
    }
}

// ---------------------------------------------------------------------------
// Kernel 2: head GEMM  out[b][o] = g_mem[b] . Wh[o] + bh[o]
// grid (BB, 4): 24 outputs per block. Reduction pattern bit-identical.
// ---------------------------------------------------------------------------
__global__ __launch_bounds__(256) void head_kernel(
    const float* __restrict__ Wh, const float* __restrict__ bh,
    float* __restrict__ out)
{
    __shared__ float s_mem[HID];
    const int b  = blockIdx.x;
    const int os = blockIdx.y * 24;           // output range [os, os+24)

    for (int i = threadIdx.x; i < HID; i += 256)
        s_mem[i] = g_mem[(size_t)b * HID + i];
    __syncthreads();

    const int warp = threadIdx.x >> 5;
    const int lane = threadIdx.x & 31;

    for (int o = os + warp; o < os + 24; o += 8) {
        const float4* w = reinterpret_cast<const float4*>(Wh + (size_t)o * HID);
        float acc = 0.0f;
#pragma unroll
        for (int h = lane; h < HID / 4; h += 32) {
            const float4 wv = w[h];
            const float4 mv = *reinterpret_cast<const float4*>(s_mem + h * 4);
            acc = fmaf(wv.x, mv.x, acc);
            acc = fmaf(wv.y, mv.y, acc);
            acc = fmaf(wv.z, mv.z, acc);
            acc = fmaf(wv.w, mv.w, acc);
        }
#pragma unroll
        for (int off = 16; off > 0; off >>= 1)
            acc += __shfl_xor_sync(0xFFFFFFFFu, acc, off);
        if (lane == 0) out[(size_t)b * HOR + o] = acc + bh[o];
    }
}

// ---------------------------------------------------------------------------
extern "C" void kernel_launch(void* const* d_in, const int* in_sizes, int n_in,
                              void* d_out, int out_size)
{
    const float* x    = (const float*)d_in[0];  // [B,T,C]
    const float* W1   = (const float*)d_in[1];  // [HID,C]
    const float* b1   = (const float*)d_in[2];  // [HID]
    const float* Wh   = (const float*)d_in[3];  // [HOR,HID]
    const float* bh   = (const float*)d_in[4];  // [HOR]
    const float* beta = (const float*)d_in[5];  // scalar
    float* out = (float*)d_out;                 // [B,HOR]

    cudaFuncSetAttribute(gemm_scan_kernel,
                         cudaFuncAttributeMaxDynamicSharedMemorySize, SMEM_TOTAL);

    convert_x_kernel<<<(MM * CC / 4) / 256, 256>>>(x);
    convert_w_kernel<<<(HID * CC / 4) / 256, 256>>>(W1);

    dim3 grid(HID / TIL_N, MM / TIL_M);   // (4, 256) = 1024 CTAs
    gemm_scan_kernel<<<grid, 256, SMEM_TOTAL>>>(b1, beta);

    dim3 hgrid(BB, 4);
    head_kernel<<<hgrid, 256>>>(Wh, bh, out);
}

// round 13
// speedup vs baseline: 2.9173x; 2.9173x over previous
#include <cuda_runtime.h>
#include <cuda_fp16.h>
#include <cstdint>

// ---------------------------------------------------------------------------
// Problem dims
// ---------------------------------------------------------------------------
#define BB   256
#define TT   128
#define CC   512
#define HID  1024
#define HOR  96
#define MM   (BB * TT)          // 32768
#define KROW 1024               // stored row length: [hi | lo] halves
#define KCH  24                 // logical K chunks of 64 halves (K_ext = 1536)
#define TIL_M 128               // = one batch (TT rows)
#define TIL_N 128
#define NSTG 3
#define A_STG_BYTES 16384       // 128 rows x 128B
#define B_STG_BYTES 16384       // 128 rows x 128B
#define STAGE_BYTES (A_STG_BYTES + B_STG_BYTES)        // 32KB
#define SMEM_TOTAL  (NSTG * STAGE_BYTES)               // 96KB/CTA, 2 CTAs/SM
#define NT   128                // threads per CTA (4 warps, 2x2 warp grid)

// ---------------------------------------------------------------------------
// Scratch (__device__ globals: allocation-free rule)
// ---------------------------------------------------------------------------
__device__ __half g_Aext[(size_t)MM * KROW];    // 64 MB  [ah | al]
__device__ __half g_Bext[(size_t)HID * KROW];   //  2 MB  [bh | bl]
__device__ float  g_mem[(size_t)BB * HID];      //  1 MB

// Logical chunk -> stored column offset (halves).
// A sequence: ah(0..7), ah(0..7), al(0..7)   B sequence: bh, bl, bh
__device__ __forceinline__ int ofsA(int kc) {
    return (kc < 16) ? (kc & 7) * 64 : 512 + (kc & 7) * 64;
}
__device__ __forceinline__ int ofsB(int kc) {
    return (kc < 8) ? kc * 64 : ((kc < 16) ? 512 + (kc & 7) * 64 : (kc & 7) * 64);
}

// ---------------------------------------------------------------------------
// Baseline-PTX helpers (sm_80-level: valid on .target sm_103)
// ---------------------------------------------------------------------------
__device__ __forceinline__ uint32_t smem_u32_of(const void* p) {
    uint32_t a;
    asm("{ .reg .u64 t; cvta.to.shared.u64 t, %1; cvt.u32.u64 %0, t; }"
        : "=r"(a) : "l"(p));
    return a;
}
__device__ __forceinline__ void cp16(uint32_t dst, const void* src) {
    asm volatile("cp.async.cg.shared.global [%0], [%1], 16;"
                 :: "r"(dst), "l"(src) : "memory");
}
__device__ __forceinline__ void cp_commit() {
    asm volatile("cp.async.commit_group;" ::: "memory");
}
__device__ __forceinline__ void ldsm4(uint32_t* r, uint32_t addr) {
    asm volatile("ldmatrix.sync.aligned.m8n8.x4.shared.b16 {%0,%1,%2,%3}, [%4];"
                 : "=r"(r[0]), "=r"(r[1]), "=r"(r[2]), "=r"(r[3]) : "r"(addr));
}
__device__ __forceinline__ void mma16816(float* c, const uint32_t* a,
                                         uint32_t b0, uint32_t b1) {
    asm volatile(
        "mma.sync.aligned.m16n8k16.row.col.f32.f16.f16.f32 "
        "{%0,%1,%2,%3}, {%4,%5,%6,%7}, {%8,%9}, {%0,%1,%2,%3};"
        : "+f"(c[0]), "+f"(c[1]), "+f"(c[2]), "+f"(c[3])
        : "r"(a[0]), "r"(a[1]), "r"(a[2]), "r"(a[3]), "r"(b0), "r"(b1));
}

// ---------------------------------------------------------------------------
// fp16 split pack helpers
// ---------------------------------------------------------------------------
__device__ __forceinline__ uint2 pack4(__half a, __half b, __half c, __half d) {
    __half2 p0 = __halves2half2(a, b);
    __half2 p1 = __halves2half2(c, d);
    uint2 u;
    u.x = *reinterpret_cast<uint32_t*>(&p0);
    u.y = *reinterpret_cast<uint32_t*>(&p1);
    return u;
}
__device__ __forceinline__ void split1(float f, __half& hi, __half& lo) {
    hi = __float2half_rn(f);
    lo = __float2half_rn(f - __half2float(hi));
}

// ---------------------------------------------------------------------------
// Kernel 0a: x [MM,CC] f32 -> g_Aext [MM, 1024] = [ah | al]
// ---------------------------------------------------------------------------
__global__ __launch_bounds__(256) void convert_x_kernel(const float* __restrict__ x)
{
    const int i = blockIdx.x * 256 + threadIdx.x;   // one float4 group
    const float4 v = reinterpret_cast<const float4*>(x)[i];
    const int m  = i >> 7;          // CC/4 = 128 groups per row
    const int k4 = i & 127;
    __half h0, h1, h2, h3, l0, l1, l2, l3;
    split1(v.x, h0, l0); split1(v.y, h1, l1);
    split1(v.z, h2, l2); split1(v.w, h3, l3);
    uint2* dst = reinterpret_cast<uint2*>(g_Aext + (size_t)m * KROW);
    dst[k4]       = pack4(h0, h1, h2, h3);   // cols   0- 511: ah
    dst[128 + k4] = pack4(l0, l1, l2, l3);   // cols 512-1023: al
}

// Kernel 0b: W1 [HID,CC] f32 -> g_Bext [HID, 1024] = [bh | bl]
__global__ __launch_bounds__(256) void convert_w_kernel(const float* __restrict__ w)
{
    const int i = blockIdx.x * 256 + threadIdx.x;   // < HID*CC/4 = 131072
    const float4 v = reinterpret_cast<const float4*>(w)[i];
    const int n  = i >> 7;
    const int k4 = i & 127;
    __half h0, h1, h2, h3, l0, l1, l2, l3;
    split1(v.x, h0, l0); split1(v.y, h1, l1);
    split1(v.z, h2, l2); split1(v.w, h3, l3);
    uint2* dst = reinterpret_cast<uint2*>(g_Bext + (size_t)n * KROW);
    dst[k4]       = pack4(h0, h1, h2, h3);   // bh
    dst[128 + k4] = pack4(l0, l1, l2, l3);   // bl
}

// ---------------------------------------------------------------------------
// Kernel 1: HMMA GEMM 128x128 per CTA, 128 threads (4 warps, warp tile
// 64x64), 2 CTAs/SM, reg cap 256 (no spills), crossbar ~96 B/cyc.
// 3-slot cp.async pipeline, depth-2 prefetch, one __syncthreads per chunk.
// Per-element accumulation order identical to all prior passing rounds.
// ---------------------------------------------------------------------------
__device__ __forceinline__ void load_stage(uint32_t smem_base, int s, int kc,
                                           int bm, int bn, int tid)
{
    const uint32_t sa = smem_base + s * STAGE_BYTES;
    const uint32_t sb = sa + A_STG_BYTES;
    const __half* ga = g_Aext + (size_t)bm * KROW + ofsA(kc);
    const __half* gb = g_Bext + (size_t)bn * KROW + ofsB(kc);
    // A: 128 rows x 8 chunks of 16B -> 1024 chunks, 8 per thread (128 thr)
#pragma unroll
    for (int j = 0; j < 8; j++) {
        const int idx = tid + j * NT;
        const int r = idx >> 3;
        const int c = idx & 7;
        uint32_t off = r * 128 + c * 16;
        off ^= (off >> 3) & 0x70;
        cp16(sa + off, ga + (size_t)r * KROW + c * 8);
    }
    // B: 128 rows x 8 chunks -> 1024 chunks, 8 per thread
#pragma unroll
    for (int j = 0; j < 8; j++) {
        const int idx = tid + j * NT;
        const int r = idx >> 3;
        const int c = idx & 7;
        uint32_t off = r * 128 + c * 16;
        off ^= (off >> 3) & 0x70;
        cp16(sb + off, gb + (size_t)r * KROW + c * 8);
    }
}

__global__ __launch_bounds__(NT, 2) void gemm_scan_kernel(
    const float* __restrict__ b1, const float* __restrict__ beta_p)
{
    extern __shared__ char smem[];
    const uint32_t smem_base = smem_u32_of(smem);
    const int tid  = threadIdx.x;
    const int lane = tid & 31;
    const int wid  = tid >> 5;
    const int wm   = wid >> 1;      // 0..1 : warp row (64 M each)
    const int wn   = wid & 1;       // 0..1 : warp col (64 N each)
    const int bm = blockIdx.y * TIL_M;
    const int bn = blockIdx.x * TIL_N;

    float c[4][8][4];               // warp tile 64x64: 4 m16 x 8 n8 frags
#pragma unroll
    for (int i = 0; i < 4; i++)
#pragma unroll
        for (int j = 0; j < 8; j++)
#pragma unroll
            for (int q = 0; q < 4; q++) c[i][j][q] = 0.0f;

    // prologue: fill slots 0..1 (depth-2 prefetch)
#pragma unroll
    for (int s = 0; s < 2; s++) {
        load_stage(smem_base, s, s, bm, bn, tid);
        cp_commit();
    }

    for (int kc = 0; kc < KCH; kc++) {
        // need chunk kc complete; chunk kc+1 may stay in flight
        if (kc < KCH - 1) asm volatile("cp.async.wait_group 1;" ::: "memory");
        else              asm volatile("cp.async.wait_group 0;" ::: "memory");
        __syncthreads();   // also: slot (kc+2)%3 == (kc-1)%3 consumed -> reusable

        // issue next prefetch BEFORE compute so LDGSTS overlaps the MMAs
        if (kc + 2 < KCH) {
            load_stage(smem_base, (kc + 2) % 3, kc + 2, bm, bn, tid);
            cp_commit();
        }

        const uint32_t sa = smem_base + (kc % 3) * STAGE_BYTES;
        const uint32_t sb = sa + A_STG_BYTES;

#pragma unroll
        for (int ks = 0; ks < 4; ks++) {      // 4 x k16 per 64-half chunk
            uint32_t af[4][4], bf[4][4];
            const uint32_t colb = ks * 32 + ((lane >> 4) << 4);  // byte col
#pragma unroll
            for (int i = 0; i < 4; i++) {
                uint32_t row = wm * 64 + i * 16 + (lane & 15);
                uint32_t off = row * 128 + colb;
                off ^= (off >> 3) & 0x70;
                ldsm4(af[i], sa + off);
            }
#pragma unroll
            for (int j = 0; j < 4; j++) {     // each covers 2 n8 frags
                uint32_t row = wn * 64 + j * 16 + (lane & 15);
                uint32_t off = row * 128 + colb;
                off ^= (off >> 3) & 0x70;
                ldsm4(bf[j], sb + off);
            }
#pragma unroll
            for (int i = 0; i < 4; i++)
#pragma unroll
                for (int j = 0; j < 4; j++) {
                    mma16816(c[i][2 * j],     af[i], bf[j][0], bf[j][2]);
                    mma16816(c[i][2 * j + 1], af[i], bf[j][1], bf[j][3]);
                }
        }
    }
    __syncthreads();   // all compute done before smem is reused as fp32 buffer

    // ------------------ fused epilogue + scan ------------------
    float* sf = reinterpret_cast<float*>(smem);   // [128][129] fp32 = 66KB
#pragma unroll
    for (int i = 0; i < 4; i++) {
        const int r0 = wm * 64 + i * 16 + (lane >> 2);
#pragma unroll
        for (int j = 0; j < 8; j++) {
            const int col = wn * 64 + j * 8 + ((lane & 3) << 1);
            sf[r0 * 129 + col]           = c[i][j][0];
            sf[r0 * 129 + col + 1]       = c[i][j][1];
            sf[(r0 + 8) * 129 + col]     = c[i][j][2];
            sf[(r0 + 8) * 129 + col + 1] = c[i][j][3];
        }
    }
    __syncthreads();

    {
        const float beta_c = fminf(fmaxf(beta_p[0], 0.0f), 1.0f);
        const float bias_h = b1[bn + tid];
        float mem = 0.0f;
#pragma unroll 8
        for (int t = 0; t < TT; t++) {
            const float inp   = sf[t * 129 + tid] + bias_h;
            const float reset = (mem > 1.0f) ? 1.0f : 0.0f;   // THR = 1.0
            mem = fmaf(beta_c, mem, inp - reset);
        }
        g_mem[(size_t)blockIdx.y * HID + bn + tid] = mem;
    }
}

// ---------------------------------------------------------------------------
// Kernel 2: head GEMM  out[b][o] = g_mem[b] . Wh[o] + bh[o]
// grid (BB, 4): 24 outputs per block. Reduction pattern bit-identical.
// ---------------------------------------------------------------------------
__global__ __launch_bounds__(256) void head_kernel(
    const float* __restrict__ Wh, const float* __restrict__ bh,
    float* __restrict__ out)
{
    __shared__ float s_mem[HID];
    const int b  = blockIdx.x;
    const int os = blockIdx.y * 24;           // output range [os, os+24)

    for (int i = threadIdx.x; i < HID; i += 256)
        s_mem[i] = g_mem[(size_t)b * HID + i];
    __syncthreads();

    const int warp = threadIdx.x >> 5;
    const int lane = threadIdx.x & 31;

    for (int o = os + warp; o < os + 24; o += 8) {
        const float4* w = reinterpret_cast<const float4*>(Wh + (size_t)o * HID);
        float acc = 0.0f;
#pragma unroll
        for (int h = lane; h < HID / 4; h += 32) {
            const float4 wv = w[h];
            const float4 mv = *reinterpret_cast<const float4*>(s_mem + h * 4);
            acc = fmaf(wv.x, mv.x, acc);
            acc = fmaf(wv.y, mv.y, acc);
            acc = fmaf(wv.z, mv.z, acc);
            acc = fmaf(wv.w, mv.w, acc);
        }
#pragma unroll
        for (int off = 16; off > 0; off >>= 1)
            acc += __shfl_xor_sync(0xFFFFFFFFu, acc, off);
        if (lane == 0) out[(size_t)b * HOR + o] = acc + bh[o];
    }
}

// ---------------------------------------------------------------------------
extern "C" void kernel_launch(void* const* d_in, const int* in_sizes, int n_in,
                              void* d_out, int out_size)
{
    const float* x    = (const float*)d_in[0];  // [B,T,C]
    const float* W1   = (const float*)d_in[1];  // [HID,C]
    const float* b1   = (const float*)d_in[2];  // [HID]
    const float* Wh   = (const float*)d_in[3];  // [HOR,HID]
    const float* bh   = (const float*)d_in[4];  // [HOR]
    const float* beta = (const float*)d_in[5];  // scalar
    float* out = (float*)d_out;                 // [B,HOR]

    cudaFuncSetAttribute(gemm_scan_kernel,
                         cudaFuncAttributeMaxDynamicSharedMemorySize, SMEM_TOTAL);

    convert_x_kernel<<<(MM * CC / 4) / 256, 256>>>(x);
    convert_w_kernel<<<(HID * CC / 4) / 256, 256>>>(W1);

    dim3 grid(HID / TIL_N, MM / TIL_M);   // (8, 256) = 2048 CTAs
    gemm_scan_kernel<<<grid, NT, SMEM_TOTAL>>>(b1, beta);

    dim3 hgrid(BB, 4);
    head_kernel<<<hgrid, 256>>>(Wh, bh, out);
}

// round 14
// speedup vs baseline: 2.9745x; 1.0196x over previous
#include <cuda_runtime.h>
#include <cuda_fp16.h>
#include <cstdint>

// ---------------------------------------------------------------------------
// Problem dims
// ---------------------------------------------------------------------------
#define BB   256
#define TT   128
#define CC   512
#define HID  1024
#define HOR  96
#define MM   (BB * TT)          // 32768
#define KROW 1024               // stored row length: [hi | lo] halves
#define KCH  24                 // logical K chunks of 64 halves (K_ext = 1536)
#define TIL_M 128               // = one batch (TT rows)
#define TIL_N 128
#define NSTG 3
#define A_STG_BYTES 16384       // 128 rows x 128B
#define B_STG_BYTES 16384       // 128 rows x 128B
#define STAGE_BYTES (A_STG_BYTES + B_STG_BYTES)        // 32KB
#define SMEM_TOTAL  (NSTG * STAGE_BYTES)               // 96KB/CTA, 2 CTAs/SM
#define NT   128                // threads per CTA (4 warps, 2x2 warp grid)

// ---------------------------------------------------------------------------
// Scratch (__device__ globals: allocation-free rule)
// ---------------------------------------------------------------------------
__device__ __half g_Aext[(size_t)MM * KROW];    // 64 MB  [ah | al]
__device__ __half g_Bext[(size_t)HID * KROW];   //  2 MB  [bh | bl]
__device__ float  g_mem[(size_t)BB * HID];      //  1 MB

// Logical chunk -> stored column offset (halves).
// A sequence: ah(0..7), ah(0..7), al(0..7)   B sequence: bh, bl, bh
__device__ __forceinline__ int ofsA(int kc) {
    return (kc < 16) ? (kc & 7) * 64 : 512 + (kc & 7) * 64;
}
__device__ __forceinline__ int ofsB(int kc) {
    return (kc < 8) ? kc * 64 : ((kc < 16) ? 512 + (kc & 7) * 64 : (kc & 7) * 64);
}

// ---------------------------------------------------------------------------
// Baseline-PTX helpers (sm_80-level: valid on .target sm_103)
// ---------------------------------------------------------------------------
__device__ __forceinline__ uint32_t smem_u32_of(const void* p) {
    uint32_t a;
    asm("{ .reg .u64 t; cvta.to.shared.u64 t, %1; cvt.u32.u64 %0, t; }"
        : "=r"(a) : "l"(p));
    return a;
}
__device__ __forceinline__ void cp16(uint32_t dst, const void* src) {
    asm volatile("cp.async.cg.shared.global [%0], [%1], 16;"
                 :: "r"(dst), "l"(src) : "memory");
}
__device__ __forceinline__ void cp_commit() {
    asm volatile("cp.async.commit_group;" ::: "memory");
}
__device__ __forceinline__ void ldsm4(uint32_t* r, uint32_t addr) {
    asm volatile("ldmatrix.sync.aligned.m8n8.x4.shared.b16 {%0,%1,%2,%3}, [%4];"
                 : "=r"(r[0]), "=r"(r[1]), "=r"(r[2]), "=r"(r[3]) : "r"(addr));
}
__device__ __forceinline__ void mma16816(float* c, const uint32_t* a,
                                         uint32_t b0, uint32_t b1) {
    asm volatile(
        "mma.sync.aligned.m16n8k16.row.col.f32.f16.f16.f32 "
        "{%0,%1,%2,%3}, {%4,%5,%6,%7}, {%8,%9}, {%0,%1,%2,%3};"
        : "+f"(c[0]), "+f"(c[1]), "+f"(c[2]), "+f"(c[3])
        : "r"(a[0]), "r"(a[1]), "r"(a[2]), "r"(a[3]), "r"(b0), "r"(b1));
}

// ---------------------------------------------------------------------------
// fp16 split pack helpers
// ---------------------------------------------------------------------------
__device__ __forceinline__ uint2 pack4(__half a, __half b, __half c, __half d) {
    __half2 p0 = __halves2half2(a, b);
    __half2 p1 = __halves2half2(c, d);
    uint2 u;
    u.x = *reinterpret_cast<uint32_t*>(&p0);
    u.y = *reinterpret_cast<uint32_t*>(&p1);
    return u;
}
__device__ __forceinline__ void split1(float f, __half& hi, __half& lo) {
    hi = __float2half_rn(f);
    lo = __float2half_rn(f - __half2float(hi));
}

// ---------------------------------------------------------------------------
// Kernel 0a: x [MM,CC] f32 -> g_Aext [MM, 1024] = [ah | al]
// ---------------------------------------------------------------------------
__global__ __launch_bounds__(256) void convert_x_kernel(const float* __restrict__ x)
{
    const int i = blockIdx.x * 256 + threadIdx.x;   // one float4 group
    const float4 v = reinterpret_cast<const float4*>(x)[i];
    const int m  = i >> 7;          // CC/4 = 128 groups per row
    const int k4 = i & 127;
    __half h0, h1, h2, h3, l0, l1, l2, l3;
    split1(v.x, h0, l0); split1(v.y, h1, l1);
    split1(v.z, h2, l2); split1(v.w, h3, l3);
    uint2* dst = reinterpret_cast<uint2*>(g_Aext + (size_t)m * KROW);
    dst[k4]       = pack4(h0, h1, h2, h3);   // cols   0- 511: ah
    dst[128 + k4] = pack4(l0, l1, l2, l3);   // cols 512-1023: al
}

// Kernel 0b: W1 [HID,CC] f32 -> g_Bext [HID, 1024] = [bh | bl]
__global__ __launch_bounds__(256) void convert_w_kernel(const float* __restrict__ w)
{
    const int i = blockIdx.x * 256 + threadIdx.x;   // < HID*CC/4 = 131072
    const float4 v = reinterpret_cast<const float4*>(w)[i];
    const int n  = i >> 7;
    const int k4 = i & 127;
    __half h0, h1, h2, h3, l0, l1, l2, l3;
    split1(v.x, h0, l0); split1(v.y, h1, l1);
    split1(v.z, h2, l2); split1(v.w, h3, l3);
    uint2* dst = reinterpret_cast<uint2*>(g_Bext + (size_t)n * KROW);
    dst[k4]       = pack4(h0, h1, h2, h3);   // bh
    dst[128 + k4] = pack4(l0, l1, l2, l3);   // bl
}

// ---------------------------------------------------------------------------
// Kernel 1: HMMA GEMM 128x128 per CTA, 128 threads (4 warps, warp tile
// 64x64), 2 CTAs/SM. All ldsm addresses precomputed (zero addr-ALU in the
// inner loop); stage rotation fully unrolled so offsets are literals.
// Per-element accumulation order identical to all prior passing rounds.
// ---------------------------------------------------------------------------
__device__ __forceinline__ void load_stage(uint32_t smem_base, int s, int kc,
                                           int bm, int bn, int tid)
{
    const uint32_t sa = smem_base + s * STAGE_BYTES;
    const uint32_t sb = sa + A_STG_BYTES;
    const __half* ga = g_Aext + (size_t)bm * KROW + ofsA(kc);
    const __half* gb = g_Bext + (size_t)bn * KROW + ofsB(kc);
    // A: 128 rows x 8 chunks of 16B -> 1024 chunks, 8 per thread (128 thr)
#pragma unroll
    for (int j = 0; j < 8; j++) {
        const int idx = tid + j * NT;
        const int r = idx >> 3;
        const int c = idx & 7;
        uint32_t off = r * 128 + c * 16;
        off ^= (off >> 3) & 0x70;
        cp16(sa + off, ga + (size_t)r * KROW + c * 8);
    }
    // B: 128 rows x 8 chunks -> 1024 chunks, 8 per thread
#pragma unroll
    for (int j = 0; j < 8; j++) {
        const int idx = tid + j * NT;
        const int r = idx >> 3;
        const int c = idx & 7;
        uint32_t off = r * 128 + c * 16;
        off ^= (off >> 3) & 0x70;
        cp16(sb + off, gb + (size_t)r * KROW + c * 8);
    }
}

// One 64-half chunk of MMAs from stage at literal byte offset SOFF.
// Addresses come from the precomputed aA/aB register arrays.
#define COMPUTE_CHUNK(SOFF)                                                   \
    do {                                                                      \
        _Pragma("unroll")                                                     \
        for (int ks = 0; ks < 4; ks++) {                                      \
            uint32_t af[4][4], bf[4][4];                                      \
            _Pragma("unroll")                                                 \
            for (int i = 0; i < 4; i++) ldsm4(af[i], aA[i * 4 + ks] + (SOFF));\
            _Pragma("unroll")                                                 \
            for (int j = 0; j < 4; j++) ldsm4(bf[j], aB[j * 4 + ks] + (SOFF));\
            _Pragma("unroll")                                                 \
            for (int i = 0; i < 4; i++)                                       \
                _Pragma("unroll")                                             \
                for (int j = 0; j < 4; j++) {                                 \
                    mma16816(c[i][2 * j],     af[i], bf[j][0], bf[j][2]);     \
                    mma16816(c[i][2 * j + 1], af[i], bf[j][1], bf[j][3]);     \
                }                                                             \
        }                                                                     \
    } while (0)

#define WAIT1 asm volatile("cp.async.wait_group 1;" ::: "memory")
#define WAIT0 asm volatile("cp.async.wait_group 0;" ::: "memory")

__global__ __launch_bounds__(NT, 2) void gemm_scan_kernel(
    const float* __restrict__ b1, const float* __restrict__ beta_p)
{
    extern __shared__ char smem[];
    const uint32_t smem_base = smem_u32_of(smem);
    const int tid  = threadIdx.x;
    const int lane = tid & 31;
    const int wid  = tid >> 5;
    const int wm   = wid >> 1;      // 0..1 : warp row (64 M each)
    const int wn   = wid & 1;       // 0..1 : warp col (64 N each)
    const int bm = blockIdx.y * TIL_M;
    const int bn = blockIdx.x * TIL_N;

    float c[4][8][4];               // warp tile 64x64: 4 m16 x 8 n8 frags
#pragma unroll
    for (int i = 0; i < 4; i++)
#pragma unroll
        for (int j = 0; j < 8; j++)
#pragma unroll
            for (int q = 0; q < 4; q++) c[i][j][q] = 0.0f;

    // Precompute all swizzled ldsm addresses for stage 0 (32 registers).
    // The swizzle XOR mask depends only on the row (bits >=7 of off), so
    // these are loop-invariant; other stages add a literal offset.
    uint32_t aA[16], aB[16];
    {
        const uint32_t l16 = (uint32_t)((lane >> 4) << 4);
#pragma unroll
        for (int i = 0; i < 4; i++) {
            const uint32_t row = wm * 64 + i * 16 + (lane & 15);
#pragma unroll
            for (int ks = 0; ks < 4; ks++) {
                uint32_t off = row * 128 + ks * 32 + l16;
                off ^= (off >> 3) & 0x70;
                aA[i * 4 + ks] = smem_base + off;
            }
        }
#pragma unroll
        for (int j = 0; j < 4; j++) {
            const uint32_t row = wn * 64 + j * 16 + (lane & 15);
#pragma unroll
            for (int ks = 0; ks < 4; ks++) {
                uint32_t off = row * 128 + ks * 32 + l16;
                off ^= (off >> 3) & 0x70;
                aB[j * 4 + ks] = smem_base + A_STG_BYTES + off;
            }
        }
    }

    // prologue: fill slots 0..1 (depth-2 prefetch)
    load_stage(smem_base, 0, 0, bm, bn, tid);
    cp_commit();
    load_stage(smem_base, 1, 1, bm, bn, tid);
    cp_commit();

    // full-rate phase: kc = 0..20 as 7 groups of 3 (slot = kc % 3 literal)
    for (int g = 0; g < 7; g++) {
        const int kcb = g * 3;
        // kc = kcb, slot 0; prefetch kcb+2 -> slot 2
        WAIT1; __syncthreads();
        load_stage(smem_base, 2, kcb + 2, bm, bn, tid); cp_commit();
        COMPUTE_CHUNK(0);
        // kc = kcb+1, slot 1; prefetch kcb+3 -> slot 0
        WAIT1; __syncthreads();
        load_stage(smem_base, 0, kcb + 3, bm, bn, tid); cp_commit();
        COMPUTE_CHUNK(STAGE_BYTES);
        // kc = kcb+2, slot 2; prefetch kcb+4 -> slot 1
        WAIT1; __syncthreads();
        load_stage(smem_base, 1, kcb + 4, bm, bn, tid); cp_commit();
        COMPUTE_CHUNK(2 * STAGE_BYTES);
    }
    // kc = 21 (slot 0): prefetch 23 -> slot 2
    WAIT1; __syncthreads();
    load_stage(smem_base, 2, 23, bm, bn, tid); cp_commit();
    COMPUTE_CHUNK(0);
    // kc = 22 (slot 1): no prefetch
    WAIT1; __syncthreads();
    COMPUTE_CHUNK(STAGE_BYTES);
    // kc = 23 (slot 2)
    WAIT0; __syncthreads();
    COMPUTE_CHUNK(2 * STAGE_BYTES);

    __syncthreads();   // all compute done before smem is reused as fp32 buffer

    // ------------------ fused epilogue + scan ------------------
    float* sf = reinterpret_cast<float*>(smem);   // [128][129] fp32 = 66KB
#pragma unroll
    for (int i = 0; i < 4; i++) {
        const int r0 = wm * 64 + i * 16 + (lane >> 2);
#pragma unroll
        for (int j = 0; j < 8; j++) {
            const int col = wn * 64 + j * 8 + ((lane & 3) << 1);
            sf[r0 * 129 + col]           = c[i][j][0];
            sf[r0 * 129 + col + 1]       = c[i][j][1];
            sf[(r0 + 8) * 129 + col]     = c[i][j][2];
            sf[(r0 + 8) * 129 + col + 1] = c[i][j][3];
        }
    }
    __syncthreads();

    {
        const float beta_c = fminf(fmaxf(beta_p[0], 0.0f), 1.0f);
        const float bias_h = b1[bn + tid];
        float mem = 0.0f;
#pragma unroll 8
        for (int t = 0; t < TT; t++) {
            const float inp   = sf[t * 129 + tid] + bias_h;
            const float reset = (mem > 1.0f) ? 1.0f : 0.0f;   // THR = 1.0
            mem = fmaf(beta_c, mem, inp - reset);
        }
        g_mem[(size_t)blockIdx.y * HID + bn + tid] = mem;
    }
}

// ---------------------------------------------------------------------------
// Kernel 2: head GEMM  out[b][o] = g_mem[b] . Wh[o] + bh[o]
// Each block: 4 batches x 24 outputs -> Wh L2 traffic /4 (head was L2-bound).
// Per-(batch,output) fma order and shfl reduction bit-identical to before.
// ---------------------------------------------------------------------------
#define HB 4
__global__ __launch_bounds__(256) void head_kernel(
    const float* __restrict__ Wh, const float* __restrict__ bh,
    float* __restrict__ out)
{
    __shared__ float s_mem[HB][HID];              // 16KB
    const int b0 = blockIdx.x * HB;
    const int os = blockIdx.y * 24;               // output range [os, os+24)

    for (int i = threadIdx.x; i < HB * HID; i += 256)
        s_mem[i >> 10][i & 1023] =
            g_mem[(size_t)(b0 + (i >> 10)) * HID + (i & 1023)];
    __syncthreads();

    const int warp = threadIdx.x >> 5;
    const int lane = threadIdx.x & 31;

    for (int o = os + warp; o < os + 24; o += 8) {
        const float4* w = reinterpret_cast<const float4*>(Wh + (size_t)o * HID);
        float acc[HB];
#pragma unroll
        for (int q = 0; q < HB; q++) acc[q] = 0.0f;
#pragma unroll
        for (int h = lane; h < HID / 4; h += 32) {
            const float4 wv = w[h];
#pragma unroll
            for (int q = 0; q < HB; q++) {
                const float4 mv =
                    *reinterpret_cast<const float4*>(&s_mem[q][h * 4]);
                acc[q] = fmaf(wv.x, mv.x, acc[q]);
                acc[q] = fmaf(wv.y, mv.y, acc[q]);
                acc[q] = fmaf(wv.z, mv.z, acc[q]);
                acc[q] = fmaf(wv.w, mv.w, acc[q]);
            }
        }
#pragma unroll
        for (int q = 0; q < HB; q++) {
            float a = acc[q];
#pragma unroll
            for (int off = 16; off > 0; off >>= 1)
                a += __shfl_xor_sync(0xFFFFFFFFu, a, off);
            if (lane == 0) out[(size_t)(b0 + q) * HOR + o] = a + bh[o];
        }
    }
}

// ---------------------------------------------------------------------------
extern "C" void kernel_launch(void* const* d_in, const int* in_sizes, int n_in,
                              void* d_out, int out_size)
{
    const float* x    = (const float*)d_in[0];  // [B,T,C]
    const float* W1   = (const float*)d_in[1];  // [HID,C]
    const float* b1   = (const float*)d_in[2];  // [HID]
    const float* Wh   = (const float*)d_in[3];  // [HOR,HID]
    const float* bh   = (const float*)d_in[4];  // [HOR]
    const float* beta = (const float*)d_in[5];  // scalar
    float* out = (float*)d_out;                 // [B,HOR]

    cudaFuncSetAttribute(gemm_scan_kernel,
                         cudaFuncAttributeMaxDynamicSharedMemorySize, SMEM_TOTAL);

    convert_x_kernel<<<(MM * CC / 4) / 256, 256>>>(x);
    convert_w_kernel<<<(HID * CC / 4) / 256, 256>>>(W1);

    dim3 grid(HID / TIL_N, MM / TIL_M);   // (8, 256) = 2048 CTAs
    gemm_scan_kernel<<<grid, NT, SMEM_TOTAL>>>(b1, beta);

    dim3 hgrid(BB / HB, 4);               // (64, 4) = 256 blocks
    head_kernel<<<hgrid, 256>>>(Wh, bh, out);
}